// round 3
// baseline (speedup 1.0000x reference)
#include <cuda_runtime.h>
#include <math.h>

#define BATCH 4
#define TT    2048
#define DD    1024

// Scratch (allocation-free rule: __device__ globals)
__device__ float g_Q[(size_t)BATCH * TT * DD];   // 32 MB
__device__ float g_K[(size_t)BATCH * TT * DD];   // 32 MB
__device__ float g_V[(size_t)BATCH * TT * DD];   // 32 MB
__device__ float g_S[(size_t)BATCH * TT * TT];   // 64 MB

// ---------------------------------------------------------------------------
// SGEMM NT:  C[M,N] = A[M,K] * B[N,K]^T   (both operands K-contiguous)
// 128x128 block, 16 K-tile, 256 threads, 8x8 microtile (4+4 split).
// causal: skip blocks with col-block > row-block + 1 (tril(k=1) mask).
// ---------------------------------------------------------------------------
__global__ __launch_bounds__(256) void sgemm_nt(
    const float* __restrict__ A, const float* __restrict__ B, float* __restrict__ C,
    int K, int lda, int ldb, int ldc,
    long long sA, long long sB, long long sC, int causal)
{
    if (causal && (int)blockIdx.x > (int)blockIdx.y + 1) return;

    const float* Ab = A + (long long)blockIdx.z * sA + (long long)blockIdx.y * 128 * lda;
    const float* Bb = B + (long long)blockIdx.z * sB + (long long)blockIdx.x * 128 * ldb;
    float*       Cb = C + (long long)blockIdx.z * sC;

    __shared__ float As[16][128];
    __shared__ float Bs[16][128];

    int tid = threadIdx.x;
    int tx  = tid & 15;
    int ty  = tid >> 4;

    float acc[8][8];
#pragma unroll
    for (int i = 0; i < 8; i++)
#pragma unroll
        for (int j = 0; j < 8; j++) acc[i][j] = 0.f;

    for (int k0 = 0; k0 < K; k0 += 16) {
#pragma unroll
        for (int l = 0; l < 2; l++) {
            int v = tid + l * 256;
            int r = v >> 2;
            int c = (v & 3) * 4;
            float4 a = *(const float4*)(Ab + (long long)r * lda + k0 + c);
            As[c + 0][r] = a.x; As[c + 1][r] = a.y;
            As[c + 2][r] = a.z; As[c + 3][r] = a.w;
            float4 b = *(const float4*)(Bb + (long long)r * ldb + k0 + c);
            Bs[c + 0][r] = b.x; Bs[c + 1][r] = b.y;
            Bs[c + 2][r] = b.z; Bs[c + 3][r] = b.w;
        }
        __syncthreads();
#pragma unroll
        for (int k = 0; k < 16; k++) {
            float4 a0 = *(const float4*)&As[k][ty * 4];
            float4 a1 = *(const float4*)&As[k][ty * 4 + 64];
            float4 b0 = *(const float4*)&Bs[k][tx * 4];
            float4 b1 = *(const float4*)&Bs[k][tx * 4 + 64];
            float av[8] = {a0.x, a0.y, a0.z, a0.w, a1.x, a1.y, a1.z, a1.w};
            float bv[8] = {b0.x, b0.y, b0.z, b0.w, b1.x, b1.y, b1.z, b1.w};
#pragma unroll
            for (int i = 0; i < 8; i++)
#pragma unroll
                for (int j = 0; j < 8; j++)
                    acc[i][j] += av[i] * bv[j];
        }
        __syncthreads();
    }

    int row0 = blockIdx.y * 128;
    int col0 = blockIdx.x * 128;
#pragma unroll
    for (int i = 0; i < 8; i++) {
        int r = row0 + ty * 4 + (i & 3) + ((i >> 2) * 64);
        float4 c0 = make_float4(acc[i][0], acc[i][1], acc[i][2], acc[i][3]);
        float4 c1 = make_float4(acc[i][4], acc[i][5], acc[i][6], acc[i][7]);
        *(float4*)(Cb + (long long)r * ldc + col0 + tx * 4)      = c0;
        *(float4*)(Cb + (long long)r * ldc + col0 + tx * 4 + 64) = c1;
    }
}

// ---------------------------------------------------------------------------
// SGEMM NN:  C[M,N] = A[M,K] * B[K,N]   (A K-contiguous, B N-contiguous)
// causal: K loop bounded to min((row_block+2)*128, K) — matches softmax
// zero-fill, so masked probs contribute exactly 0.
// ---------------------------------------------------------------------------
__global__ __launch_bounds__(256) void sgemm_nn(
    const float* __restrict__ A, const float* __restrict__ B, float* __restrict__ C,
    int K, int lda, int ldb, int ldc,
    long long sA, long long sB, long long sC, int causal)
{
    const float* Ab = A + (long long)blockIdx.z * sA + (long long)blockIdx.y * 128 * lda;
    const float* Bb = B + (long long)blockIdx.z * sB + (long long)blockIdx.x * 128;
    float*       Cb = C + (long long)blockIdx.z * sC;

    int Kend = causal ? min(((int)blockIdx.y + 2) * 128, K) : K;

    __shared__ float As[16][128];
    __shared__ float Bs[16][128];

    int tid = threadIdx.x;
    int tx  = tid & 15;
    int ty  = tid >> 4;

    float acc[8][8];
#pragma unroll
    for (int i = 0; i < 8; i++)
#pragma unroll
        for (int j = 0; j < 8; j++) acc[i][j] = 0.f;

    for (int k0 = 0; k0 < Kend; k0 += 16) {
#pragma unroll
        for (int l = 0; l < 2; l++) {
            int v = tid + l * 256;
            // A tile: 128 rows x 16 K  (K-contiguous)
            int r = v >> 2;
            int c = (v & 3) * 4;
            float4 a = *(const float4*)(Ab + (long long)r * lda + k0 + c);
            As[c + 0][r] = a.x; As[c + 1][r] = a.y;
            As[c + 2][r] = a.z; As[c + 3][r] = a.w;
            // B tile: 16 K-rows x 128 cols (N-contiguous) — direct vector store
            int br = v >> 5;
            int bc = (v & 31) * 4;
            float4 b = *(const float4*)(Bb + (long long)(k0 + br) * ldb + bc);
            *(float4*)&Bs[br][bc] = b;
        }
        __syncthreads();
#pragma unroll
        for (int k = 0; k < 16; k++) {
            float4 a0 = *(const float4*)&As[k][ty * 4];
            float4 a1 = *(const float4*)&As[k][ty * 4 + 64];
            float4 b0 = *(const float4*)&Bs[k][tx * 4];
            float4 b1 = *(const float4*)&Bs[k][tx * 4 + 64];
            float av[8] = {a0.x, a0.y, a0.z, a0.w, a1.x, a1.y, a1.z, a1.w};
            float bv[8] = {b0.x, b0.y, b0.z, b0.w, b1.x, b1.y, b1.z, b1.w};
#pragma unroll
            for (int i = 0; i < 8; i++)
#pragma unroll
                for (int j = 0; j < 8; j++)
                    acc[i][j] += av[i] * bv[j];
        }
        __syncthreads();
    }

    int row0 = blockIdx.y * 128;
    int col0 = blockIdx.x * 128;
#pragma unroll
    for (int i = 0; i < 8; i++) {
        int r = row0 + ty * 4 + (i & 3) + ((i >> 2) * 64);
        float4 c0 = make_float4(acc[i][0], acc[i][1], acc[i][2], acc[i][3]);
        float4 c1 = make_float4(acc[i][4], acc[i][5], acc[i][6], acc[i][7]);
        *(float4*)(Cb + (long long)r * ldc + col0 + tx * 4)      = c0;
        *(float4*)(Cb + (long long)r * ldc + col0 + tx * 4 + 64) = c1;
    }
}

// ---------------------------------------------------------------------------
// RoPE in place. Pair i of row (b,t): theta = 10000^(-2i/d).
// theta + sincos in fp64 (fast-math powf would give ~1e-2 output error at
// ang ~ 2000 rad); the t*theta multiply stays fp32 to mirror the reference.
// blockIdx.y: 0 -> Q, 1 -> K.
// ---------------------------------------------------------------------------
__global__ __launch_bounds__(256) void rope_kernel(float* __restrict__ Q,
                                                   float* __restrict__ Kb)
{
    unsigned idx = blockIdx.x * 256u + threadIdx.x;     // < B*T*512
    float* P = (blockIdx.y == 0) ? Q : Kb;
    int i = idx & 511;            // pair index, half = 512
    int t = (idx >> 9) & (TT - 1);

    // ln(10000) = 9.210340371976184
    float theta = (float)exp(-2.0 * (double)i / (double)DD * 9.210340371976184);
    float ang   = (float)t * theta;
    double sd, cd;
    sincos((double)ang, &sd, &cd);
    float c = (float)cd, s = (float)sd;

    size_t base = (size_t)idx * 2;
    float e = P[base], o = P[base + 1];
    P[base]     = e * c - o * s;
    P[base + 1] = e * s + o * c;
}

// ---------------------------------------------------------------------------
// Row softmax over valid prefix j <= q+1 (tril k=1), scale 1/sqrt(d)=1/32.
// Row slice lives in registers (<= 8 elems/thread). Zero-fills masked region
// up to the 128-aligned bound the PV GEMM will read.
// ---------------------------------------------------------------------------
__global__ __launch_bounds__(256) void softmax_rows(float* __restrict__ S)
{
    int row = blockIdx.x;                 // b*T + q
    int q   = row & (TT - 1);
    float* s = S + (size_t)row * TT;
    int n    = min(q + 2, TT);                         // valid count
    int zend = min((((q >> 7) + 2) << 7), TT);         // PV read bound

    int tid = threadIdx.x;
    float vals[8];
    int cnt = 0;
    float m = -1e30f;
    for (int j = tid; j < n; j += 256) {
        float v = s[j];
        vals[cnt++] = v;
        m = fmaxf(m, v);
    }

    __shared__ float red[8];
#pragma unroll
    for (int o = 16; o; o >>= 1) m = fmaxf(m, __shfl_xor_sync(0xffffffffu, m, o));
    if ((tid & 31) == 0) red[tid >> 5] = m;
    __syncthreads();
    m = red[0];
#pragma unroll
    for (int w = 1; w < 8; w++) m = fmaxf(m, red[w]);
    __syncthreads();

    float sum = 0.f;
    for (int c = 0; c < cnt; c++) {
        float e = expf((vals[c] - m) * 0.03125f);
        vals[c] = e;
        sum += e;
    }
#pragma unroll
    for (int o = 16; o; o >>= 1) sum += __shfl_xor_sync(0xffffffffu, sum, o);
    if ((tid & 31) == 0) red[tid >> 5] = sum;
    __syncthreads();
    float tot = 0.f;
#pragma unroll
    for (int w = 0; w < 8; w++) tot += red[w];
    float inv = 1.0f / tot;

    cnt = 0;
    for (int j = tid; j < n; j += 256) s[j] = vals[cnt++] * inv;
    for (int j = n + tid; j < zend; j += 256) s[j] = 0.f;
}

// ---------------------------------------------------------------------------
// Launch: QKV gemms -> RoPE -> scores (causal-skip) -> softmax -> PV
// ---------------------------------------------------------------------------
extern "C" void kernel_launch(void* const* d_in, const int* in_sizes, int n_in,
                              void* d_out, int out_size)
{
    const float* x  = (const float*)d_in[0];
    const float* Wq = (const float*)d_in[1];
    const float* Wk = (const float*)d_in[2];
    const float* Wv = (const float*)d_in[3];
    float* out = (float*)d_out;

    float *Q, *K, *V, *S;
    cudaGetSymbolAddress((void**)&Q, g_Q);
    cudaGetSymbolAddress((void**)&K, g_K);
    cudaGetSymbolAddress((void**)&V, g_V);
    cudaGetSymbolAddress((void**)&S, g_S);

    dim3 blk(256);
    const long long TD = (long long)TT * DD;
    const long long TT2 = (long long)TT * TT;

    // QKV: C[8192,1024] = X[8192,1024] * W[1024,1024]^T
    dim3 gq(DD / 128, (BATCH * TT) / 128, 1);
    sgemm_nt<<<gq, blk>>>(x, Wq, Q, DD, DD, DD, DD, 0, 0, 0, 0);
    sgemm_nt<<<gq, blk>>>(x, Wk, K, DD, DD, DD, DD, 0, 0, 0, 0);
    sgemm_nt<<<gq, blk>>>(x, Wv, V, DD, DD, DD, DD, 0, 0, 0, 0);

    // RoPE on Q and K in place
    rope_kernel<<<dim3((BATCH * TT * (DD / 2)) / 256, 2), blk>>>(Q, K);

    // Scores: S[b] = Qr[b] * Kr[b]^T  (raw, unscaled; causal block skip)
    sgemm_nt<<<dim3(TT / 128, TT / 128, BATCH), blk>>>(
        Q, K, S, DD, DD, DD, TT, TD, TD, TT2, 1);

    // Softmax (applies 1/32 scale, causal mask, zero-fill)
    softmax_rows<<<BATCH * TT, blk>>>(S);

    // Out: O[b] = P[b] * V[b]   (K bounded per q-block)
    sgemm_nn<<<dim3(DD / 128, TT / 128, BATCH), blk>>>(
        S, V, out, TT, TT, DD, DD, TT2, TD, TD, 1);
}

// round 5
// speedup vs baseline: 3.4240x; 3.4240x over previous
#include <cuda_runtime.h>
#include <math.h>
#include <stdint.h>

#define BATCH 4
#define TT    2048
#define DD    1024
#define HALF_D 512

// Scratch (allocation-free rule: __device__ globals)
__device__ float g_Q[(size_t)BATCH * TT * DD];   // 32 MB
__device__ float g_K[(size_t)BATCH * TT * DD];   // 32 MB
__device__ float g_V[(size_t)BATCH * TT * DD];   // 32 MB
__device__ float g_S[(size_t)BATCH * TT * TT];   // 64 MB
__device__ float g_cosT[(size_t)TT * HALF_D];    // 4 MB
__device__ float g_sinT[(size_t)TT * HALF_D];    // 4 MB

// ---------------------------------------------------------------------------
// helpers
// ---------------------------------------------------------------------------
__device__ __forceinline__ float to_tf32(float x) {
    uint32_t y;
    asm("cvt.rna.tf32.f32 %0, %1;" : "=r"(y) : "f"(x));
    return __uint_as_float(y);
}

__device__ __forceinline__ void ldsm_x4(uint32_t f[4], uint32_t addr) {
    asm volatile("ldmatrix.sync.aligned.m8n8.x4.shared.b16 {%0,%1,%2,%3}, [%4];"
                 : "=r"(f[0]), "=r"(f[1]), "=r"(f[2]), "=r"(f[3]) : "r"(addr));
}
__device__ __forceinline__ void ldsm_x2(uint32_t f[2], uint32_t addr) {
    asm volatile("ldmatrix.sync.aligned.m8n8.x2.shared.b16 {%0,%1}, [%2];"
                 : "=r"(f[0]), "=r"(f[1]) : "r"(addr));
}

__device__ __forceinline__ void mma_tf32(float c[4], const uint32_t a[4],
                                         const uint32_t b[2]) {
    asm volatile(
        "mma.sync.aligned.m16n8k8.row.col.f32.tf32.tf32.f32 "
        "{%0,%1,%2,%3},{%4,%5,%6,%7},{%8,%9},{%0,%1,%2,%3};"
        : "+f"(c[0]), "+f"(c[1]), "+f"(c[2]), "+f"(c[3])
        : "r"(a[0]), "r"(a[1]), "r"(a[2]), "r"(a[3]), "r"(b[0]), "r"(b[1]));
}

// ---------------------------------------------------------------------------
// RoPE cos/sin table. Reference rounds ang = t*theta in fp32 BEFORE cos, so we
// do the same; then fp64 range-reduce the fp32 angle and take sinf/cosf
// (avoids the fp64 sincos that cost 739us last round).
// ---------------------------------------------------------------------------
__global__ __launch_bounds__(256) void rope_table(float* __restrict__ cosT,
                                                  float* __restrict__ sinT)
{
    unsigned idx = blockIdx.x * 256u + threadIdx.x;   // < TT*HALF_D
    int i = idx & (HALF_D - 1);
    int t = idx >> 9;
    float theta = (float)exp(-2.0 * (double)i / (double)DD * 9.210340371976184);
    float ang   = (float)t * theta;                   // fp32, matches reference
    double x = (double)ang;
    double k = floor(x * 0.15915494309189535);        // x / 2pi
    float  r = (float)(x - k * 6.283185307179586);
    cosT[idx] = cosf(r);
    sinT[idx] = sinf(r);
}

// ---------------------------------------------------------------------------
// TF32 MMA GEMM, NT:  C[M,N] = A[M,K] * B[N,K]^T   (both K-contiguous)
// Block 128x128, BK=32, 256 threads = 8 warps (2x4), warp tile 64x32.
// causal: skip blocks with bx > by+1. rope: rotate adjacent col pairs
// using cos/sin table indexed by (row & 2047, col/2).
// ---------------------------------------------------------------------------
__global__ __launch_bounds__(256) void mma_nt(
    const float* __restrict__ A, const float* __restrict__ B, float* __restrict__ C,
    int K, int lda, int ldb, int ldc,
    long long sA, long long sB, long long sC,
    int causal, int rope,
    const float* __restrict__ cosT, const float* __restrict__ sinT)
{
    if (causal && (int)blockIdx.x > (int)blockIdx.y + 1) return;

    const float* Ab = A + (long long)blockIdx.z * sA + (long long)blockIdx.y * 128 * lda;
    const float* Bb = B + (long long)blockIdx.z * sB + (long long)blockIdx.x * 128 * ldb;
    float*       Cb = C + (long long)blockIdx.z * sC;

    __shared__ float As[128][36];   // [row][k], stride 36 -> ldmatrix conflict-free
    __shared__ float Bs[128][36];   // [n][k]

    int tid  = threadIdx.x;
    int lane = tid & 31, warp = tid >> 5;
    int wy = warp >> 2, wx = warp & 3;      // warp rows wy*64, cols wx*32
    int grp = lane >> 2, l4 = lane & 3;

    uint32_t as_base = (uint32_t)__cvta_generic_to_shared(&As[0][0]);
    uint32_t bs_base = (uint32_t)__cvta_generic_to_shared(&Bs[0][0]);

    // ldmatrix per-lane address components
    int a_row = lane & 15;            // + m0
    int a_k   = (lane >> 4) * 4;      // + kb
    int b_row = lane & 7;             // + n0
    int b_k   = ((lane >> 3) & 1) * 4;

    float acc[4][4][4];
#pragma unroll
    for (int mt = 0; mt < 4; mt++)
#pragma unroll
        for (int nt = 0; nt < 4; nt++)
#pragma unroll
            for (int j = 0; j < 4; j++) acc[mt][nt][j] = 0.f;

    for (int k0 = 0; k0 < K; k0 += 32) {
#pragma unroll
        for (int l = 0; l < 4; l++) {
            int v = tid + l * 256;
            int r = v >> 3;
            int c = (v & 7) * 4;
            float4 a = *(const float4*)(Ab + (long long)r * lda + k0 + c);
            a.x = to_tf32(a.x); a.y = to_tf32(a.y);
            a.z = to_tf32(a.z); a.w = to_tf32(a.w);
            *(float4*)&As[r][c] = a;
            float4 b = *(const float4*)(Bb + (long long)r * ldb + k0 + c);
            b.x = to_tf32(b.x); b.y = to_tf32(b.y);
            b.z = to_tf32(b.z); b.w = to_tf32(b.w);
            *(float4*)&Bs[r][c] = b;
        }
        __syncthreads();
#pragma unroll
        for (int ks = 0; ks < 4; ks++) {
            int kb = ks * 8;
            uint32_t afr[4][4], bfr[4][2];
#pragma unroll
            for (int mt = 0; mt < 4; mt++) {
                int row = wy * 64 + mt * 16 + a_row;
                ldsm_x4(afr[mt], as_base + ((row * 36 + kb + a_k) << 2));
            }
#pragma unroll
            for (int nt = 0; nt < 4; nt++) {
                int row = wx * 32 + nt * 8 + b_row;
                ldsm_x2(bfr[nt], bs_base + ((row * 36 + kb + b_k) << 2));
            }
#pragma unroll
            for (int mt = 0; mt < 4; mt++)
#pragma unroll
                for (int nt = 0; nt < 4; nt++)
                    mma_tf32(acc[mt][nt], afr[mt], bfr[nt]);
        }
        __syncthreads();
    }

    int row0 = blockIdx.y * 128 + wy * 64;
    int col0 = blockIdx.x * 128 + wx * 32;
#pragma unroll
    for (int mt = 0; mt < 4; mt++) {
        int r1 = row0 + mt * 16 + grp;
        int r2 = r1 + 8;
#pragma unroll
        for (int nt = 0; nt < 4; nt++) {
            int cc = col0 + nt * 8 + l4 * 2;
            float e0 = acc[mt][nt][0], o0 = acc[mt][nt][1];
            float e1 = acc[mt][nt][2], o1 = acc[mt][nt][3];
            if (rope) {
                int p  = cc >> 1;
                int t1 = r1 & (TT - 1), t2 = r2 & (TT - 1);
                float c1v = cosT[t1 * HALF_D + p], s1v = sinT[t1 * HALF_D + p];
                float c2v = cosT[t2 * HALF_D + p], s2v = sinT[t2 * HALF_D + p];
                float ne0 = e0 * c1v - o0 * s1v, no0 = e0 * s1v + o0 * c1v;
                float ne1 = e1 * c2v - o1 * s2v, no1 = e1 * s2v + o1 * c2v;
                e0 = ne0; o0 = no0; e1 = ne1; o1 = no1;
            }
            *(float2*)(Cb + (long long)r1 * ldc + cc) = make_float2(e0, o0);
            *(float2*)(Cb + (long long)r2 * ldc + cc) = make_float2(e1, o1);
        }
    }
}

// ---------------------------------------------------------------------------
// TF32 MMA GEMM, NN:  C[M,N] = A[M,K] * B[K,N]   (A K-contig, B N-contig)
// causal: K bounded to min((by+2)*128, K) — matches softmax zero-fill.
// ---------------------------------------------------------------------------
__global__ __launch_bounds__(256) void mma_nn(
    const float* __restrict__ A, const float* __restrict__ B, float* __restrict__ C,
    int K, int lda, int ldb, int ldc,
    long long sA, long long sB, long long sC, int causal)
{
    const float* Ab = A + (long long)blockIdx.z * sA + (long long)blockIdx.y * 128 * lda;
    const float* Bb = B + (long long)blockIdx.z * sB + (long long)blockIdx.x * 128;
    float*       Cb = C + (long long)blockIdx.z * sC;

    int Kend = causal ? min(((int)blockIdx.y + 2) * 128, K) : K;

    __shared__ float As[128][36];    // [row][k]
    __shared__ float Bs2[32][136];   // [k][n], stride 136 -> conflict-free frag LDS

    int tid  = threadIdx.x;
    int lane = tid & 31, warp = tid >> 5;
    int wy = warp >> 2, wx = warp & 3;
    int grp = lane >> 2, l4 = lane & 3;

    uint32_t as_base = (uint32_t)__cvta_generic_to_shared(&As[0][0]);

    int a_row = lane & 15;
    int a_k   = (lane >> 4) * 4;

    float acc[4][4][4];
#pragma unroll
    for (int mt = 0; mt < 4; mt++)
#pragma unroll
        for (int nt = 0; nt < 4; nt++)
#pragma unroll
            for (int j = 0; j < 4; j++) acc[mt][nt][j] = 0.f;

    for (int k0 = 0; k0 < Kend; k0 += 32) {
#pragma unroll
        for (int l = 0; l < 4; l++) {
            int v = tid + l * 256;
            int r = v >> 3;
            int c = (v & 7) * 4;
            float4 a = *(const float4*)(Ab + (long long)r * lda + k0 + c);
            a.x = to_tf32(a.x); a.y = to_tf32(a.y);
            a.z = to_tf32(a.z); a.w = to_tf32(a.w);
            *(float4*)&As[r][c] = a;
            int br = v >> 5;            // 0..31
            int bc = (v & 31) * 4;      // 0..124
            float4 b = *(const float4*)(Bb + (long long)(k0 + br) * ldb + bc);
            b.x = to_tf32(b.x); b.y = to_tf32(b.y);
            b.z = to_tf32(b.z); b.w = to_tf32(b.w);
            *(float4*)&Bs2[br][bc] = b;
        }
        __syncthreads();
#pragma unroll
        for (int ks = 0; ks < 4; ks++) {
            int kb = ks * 8;
            uint32_t afr[4][4], bfr[4][2];
#pragma unroll
            for (int mt = 0; mt < 4; mt++) {
                int row = wy * 64 + mt * 16 + a_row;
                ldsm_x4(afr[mt], as_base + ((row * 36 + kb + a_k) << 2));
            }
#pragma unroll
            for (int nt = 0; nt < 4; nt++) {
                int n = wx * 32 + nt * 8 + grp;
                bfr[nt][0] = __float_as_uint(Bs2[kb + l4][n]);
                bfr[nt][1] = __float_as_uint(Bs2[kb + l4 + 4][n]);
            }
#pragma unroll
            for (int mt = 0; mt < 4; mt++)
#pragma unroll
                for (int nt = 0; nt < 4; nt++)
                    mma_tf32(acc[mt][nt], afr[mt], bfr[nt]);
        }
        __syncthreads();
    }

    int row0 = blockIdx.y * 128 + wy * 64;
    int col0 = blockIdx.x * 128 + wx * 32;
#pragma unroll
    for (int mt = 0; mt < 4; mt++) {
        int r1 = row0 + mt * 16 + grp;
        int r2 = r1 + 8;
#pragma unroll
        for (int nt = 0; nt < 4; nt++) {
            int cc = col0 + nt * 8 + l4 * 2;
            *(float2*)(Cb + (long long)r1 * ldc + cc) =
                make_float2(acc[mt][nt][0], acc[mt][nt][1]);
            *(float2*)(Cb + (long long)r2 * ldc + cc) =
                make_float2(acc[mt][nt][2], acc[mt][nt][3]);
        }
    }
}

// ---------------------------------------------------------------------------
// Row softmax over valid prefix j <= q+1 (tril k=1), scale 1/sqrt(d)=1/32.
// Zero-fills masked region up to the 128-aligned bound the PV GEMM reads.
// ---------------------------------------------------------------------------
__global__ __launch_bounds__(256) void softmax_rows(float* __restrict__ S)
{
    int row = blockIdx.x;                 // b*T + q
    int q   = row & (TT - 1);
    float* s = S + (size_t)row * TT;
    int n    = min(q + 2, TT);
    int zend = min((((q >> 7) + 2) << 7), TT);

    int tid = threadIdx.x;
    float vals[8];
    int cnt = 0;
    float m = -1e30f;
    for (int j = tid; j < n; j += 256) {
        float v = s[j];
        vals[cnt++] = v;
        m = fmaxf(m, v);
    }

    __shared__ float red[8];
#pragma unroll
    for (int o = 16; o; o >>= 1) m = fmaxf(m, __shfl_xor_sync(0xffffffffu, m, o));
    if ((tid & 31) == 0) red[tid >> 5] = m;
    __syncthreads();
    m = red[0];
#pragma unroll
    for (int w = 1; w < 8; w++) m = fmaxf(m, red[w]);
    __syncthreads();

    float sum = 0.f;
    for (int c = 0; c < cnt; c++) {
        float e = expf((vals[c] - m) * 0.03125f);
        vals[c] = e;
        sum += e;
    }
#pragma unroll
    for (int o = 16; o; o >>= 1) sum += __shfl_xor_sync(0xffffffffu, sum, o);
    if ((tid & 31) == 0) red[tid >> 5] = sum;
    __syncthreads();
    float tot = 0.f;
#pragma unroll
    for (int w = 0; w < 8; w++) tot += red[w];
    float inv = 1.0f / tot;

    cnt = 0;
    for (int j = tid; j < n; j += 256) s[j] = vals[cnt++] * inv;
    for (int j = n + tid; j < zend; j += 256) s[j] = 0.f;
}

// ---------------------------------------------------------------------------
// Launch: table -> QKV gemms (rope fused for Q,K) -> scores -> softmax -> PV
// ---------------------------------------------------------------------------
extern "C" void kernel_launch(void* const* d_in, const int* in_sizes, int n_in,
                              void* d_out, int out_size)
{
    const float* x  = (const float*)d_in[0];
    const float* Wq = (const float*)d_in[1];
    const float* Wk = (const float*)d_in[2];
    const float* Wv = (const float*)d_in[3];
    float* out = (float*)d_out;

    float *Q, *K, *V, *S, *cT, *sT;
    cudaGetSymbolAddress((void**)&Q,  g_Q);
    cudaGetSymbolAddress((void**)&K,  g_K);
    cudaGetSymbolAddress((void**)&V,  g_V);
    cudaGetSymbolAddress((void**)&S,  g_S);
    cudaGetSymbolAddress((void**)&cT, g_cosT);
    cudaGetSymbolAddress((void**)&sT, g_sinT);

    dim3 blk(256);
    const long long TD  = (long long)TT * DD;
    const long long TT2 = (long long)TT * TT;

    rope_table<<<(TT * HALF_D) / 256, blk>>>(cT, sT);

    // QKV: C[8192,1024] = X[8192,1024] * W[1024,1024]^T  (rope fused for Q,K)
    dim3 gq(DD / 128, (BATCH * TT) / 128, 1);
    mma_nt<<<gq, blk>>>(x, Wq, Q, DD, DD, DD, DD, 0, 0, 0, 0, 1, cT, sT);
    mma_nt<<<gq, blk>>>(x, Wk, K, DD, DD, DD, DD, 0, 0, 0, 0, 1, cT, sT);
    mma_nt<<<gq, blk>>>(x, Wv, V, DD, DD, DD, DD, 0, 0, 0, 0, 0, cT, sT);

    // Scores: S[b] = Qr[b] * Kr[b]^T  (raw; causal block skip)
    mma_nt<<<dim3(TT / 128, TT / 128, BATCH), blk>>>(
        Q, K, S, DD, DD, DD, TT, TD, TD, TT2, 1, 0, cT, sT);

    // Softmax (scale 1/32, causal mask, zero-fill)
    softmax_rows<<<BATCH * TT, blk>>>(S);

    // Out: O[b] = P[b] * V[b]   (K bounded per q-block)
    mma_nn<<<dim3(DD / 128, TT / 128, BATCH), blk>>>(
        S, V, out, TT, TT, DD, DD, TT2, TD, TD, 1);
}

// round 7
// speedup vs baseline: 5.4208x; 1.5832x over previous
#include <cuda_runtime.h>
#include <math.h>
#include <stdint.h>

#define BATCH 4
#define TT    2048
#define DD    1024
#define HALF_D 512

// Scratch (allocation-free rule: __device__ globals)
__device__ float g_Q[(size_t)BATCH * TT * DD];   // 32 MB
__device__ float g_K[(size_t)BATCH * TT * DD];   // 32 MB
__device__ float g_V[(size_t)BATCH * TT * DD];   // 32 MB
__device__ float g_S[(size_t)BATCH * TT * TT];   // 64 MB (first 44MB aliased as x_t/W_t before scores)
__device__ float g_cosT[(size_t)TT * HALF_D];    // 4 MB
__device__ float g_sinT[(size_t)TT * HALF_D];    // 4 MB

// ---------------------------------------------------------------------------
// helpers
// ---------------------------------------------------------------------------
__device__ __forceinline__ float tf32f(float x) {
    uint32_t y;
    asm("cvt.rna.tf32.f32 %0, %1;" : "=r"(y) : "f"(x));
    return __uint_as_float(y);
}
__device__ __forceinline__ void cp16(uint32_t dst, const void* src) {
    asm volatile("cp.async.cg.shared.global [%0], [%1], 16;" :: "r"(dst), "l"(src));
}
__device__ __forceinline__ void cp_commit() { asm volatile("cp.async.commit_group;"); }
__device__ __forceinline__ void cp_wait1()  { asm volatile("cp.async.wait_group 1;"); }

__device__ __forceinline__ void ldsm_x4(uint32_t f[4], uint32_t addr) {
    asm volatile("ldmatrix.sync.aligned.m8n8.x4.shared.b16 {%0,%1,%2,%3}, [%4];"
                 : "=r"(f[0]), "=r"(f[1]), "=r"(f[2]), "=r"(f[3]) : "r"(addr));
}
__device__ __forceinline__ void ldsm_x2(uint32_t f[2], uint32_t addr) {
    asm volatile("ldmatrix.sync.aligned.m8n8.x2.shared.b16 {%0,%1}, [%2];"
                 : "=r"(f[0]), "=r"(f[1]) : "r"(addr));
}
__device__ __forceinline__ void mma_tf32(float c[4], const uint32_t a[4],
                                         const uint32_t b[2]) {
    asm volatile(
        "mma.sync.aligned.m16n8k8.row.col.f32.tf32.tf32.f32 "
        "{%0,%1,%2,%3},{%4,%5,%6,%7},{%8,%9},{%0,%1,%2,%3};"
        : "+f"(c[0]), "+f"(c[1]), "+f"(c[2]), "+f"(c[3])
        : "r"(a[0]), "r"(a[1]), "r"(a[2]), "r"(a[3]), "r"(b[0]), "r"(b[1]));
}

// ---------------------------------------------------------------------------
// RoPE cos/sin table (fp64 range-reduction, matches reference fp32 angle round)
// ---------------------------------------------------------------------------
__global__ __launch_bounds__(256) void rope_table(float* __restrict__ cosT,
                                                  float* __restrict__ sinT)
{
    unsigned idx = blockIdx.x * 256u + threadIdx.x;   // < TT*HALF_D
    int i = idx & (HALF_D - 1);
    int t = idx >> 9;
    float theta = (float)exp(-2.0 * (double)i / (double)DD * 9.210340371976184);
    float ang   = (float)t * theta;                   // fp32, matches reference
    double x = (double)ang;
    double k = floor(x * 0.15915494309189535);        // x / 2pi
    float  r = (float)(x - k * 6.283185307179586);
    cosT[idx] = cosf(r);
    sinT[idx] = sinf(r);
}

// ---------------------------------------------------------------------------
// Pre-round fp32 -> tf32 (vectorized). Output buffers feed the GEMMs so the
// mainloops need no cvt instructions at all.
// ---------------------------------------------------------------------------
__global__ __launch_bounds__(256) void round_in(const float4* __restrict__ s,
                                                float4* __restrict__ d, int n)
{
    int i = blockIdx.x * 256 + threadIdx.x;
    if (i < n) {
        float4 v = s[i];
        v.x = tf32f(v.x); v.y = tf32f(v.y);
        v.z = tf32f(v.z); v.w = tf32f(v.w);
        d[i] = v;
    }
}

// ---------------------------------------------------------------------------
// TF32 MMA GEMM, NT: C[M,N] = A[M,K]*B[N,K]^T. Inputs already tf32-rounded.
// 128x128 block, BK=32, 256 thr, 8 warps (2x4), warp tile 64x32.
// 3-stage cp.async pipeline, XOR-swizzled smem (row=128B, chunk^=(row&7)).
// qkv mode: blockIdx.z selects W/out matrix; rope fused for z<2; output
//           tf32-rounded (consumed by the scores GEMM).
// scores mode (qkv=0): z=batch, causal block skip, raw fp32 output.
// ---------------------------------------------------------------------------
__global__ __launch_bounds__(256, 2) void mma_nt(
    const float* __restrict__ A,
    const float* __restrict__ B0, const float* __restrict__ B1, const float* __restrict__ B2,
    float* __restrict__ C0, float* __restrict__ C1, float* __restrict__ C2,
    int K, int lda, int ldb, int ldc,
    long long sA, long long sB, long long sC,
    int qkv,
    const float* __restrict__ cosT, const float* __restrict__ sinT)
{
    int bz = blockIdx.z;
    const float* Ap = A;
    const float* Bp; float* Cp; int rope;
    if (qkv) {
        Bp = (bz == 0) ? B0 : ((bz == 1) ? B1 : B2);
        Cp = (bz == 0) ? C0 : ((bz == 1) ? C1 : C2);
        rope = (bz < 2) ? 1 : 0;
    } else {
        if ((int)blockIdx.x > (int)blockIdx.y + 1) return;
        Ap = A  + (long long)bz * sA;
        Bp = B0 + (long long)bz * sB;
        Cp = C0 + (long long)bz * sC;
        rope = 0;
    }
    const float* Ab = Ap + (long long)blockIdx.y * 128 * lda;
    const float* Bb = Bp + (long long)blockIdx.x * 128 * ldb;

    extern __shared__ float sm[];
    uint32_t su = (uint32_t)__cvta_generic_to_shared(sm);

    int tid = threadIdx.x, lane = tid & 31, warp = tid >> 5;
    int wy = warp >> 2, wx = warp & 3;
    int grp = lane >> 2, l4 = lane & 3;

    int arow_l = lane & 15;
    int ak_h   = lane >> 4;
    int brow_l = lane & 7;
    int bk_h   = (lane >> 3) & 1;

    float acc[4][4][4];
#pragma unroll
    for (int mt = 0; mt < 4; mt++)
#pragma unroll
        for (int nt = 0; nt < 4; nt++)
#pragma unroll
            for (int j = 0; j < 4; j++) acc[mt][nt][j] = 0.f;

    int ntiles = K >> 5;

    // ---- tile loader (stage stride 32768B: A 16KB, B 16KB) ----
#define NT_LOAD(stage, k0)                                                    \
    {                                                                         \
        uint32_t sa_ = su + (stage) * 32768;                                  \
        _Pragma("unroll")                                                     \
        for (int l = 0; l < 4; l++) {                                         \
            int v = tid + l * 256;                                            \
            int r = v >> 3, c4 = v & 7;                                       \
            uint32_t off = (uint32_t)(r * 128 + ((c4 ^ (r & 7)) << 4));       \
            cp16(sa_ + off,         Ab + (long long)r * lda + (k0) + c4 * 4); \
            cp16(sa_ + 16384 + off, Bb + (long long)r * ldb + (k0) + c4 * 4); \
        }                                                                     \
    }

    NT_LOAD(0, 0);  cp_commit();
    NT_LOAD(1, 32); cp_commit();

    int rs = 0;
    for (int t = 0; t < ntiles; t++) {
        cp_wait1();
        __syncthreads();
        uint32_t sa = su + rs * 32768;
        uint32_t sb = sa + 16384;
#pragma unroll
        for (int ks = 0; ks < 4; ks++) {
            int kc = ks * 2;
            uint32_t afr[4][4], bfr[4][2];
#pragma unroll
            for (int mt = 0; mt < 4; mt++) {
                int row = wy * 64 + mt * 16 + arow_l;
                int ch  = (kc + ak_h) ^ (row & 7);
                ldsm_x4(afr[mt], sa + (uint32_t)(row * 128 + (ch << 4)));
            }
#pragma unroll
            for (int nt = 0; nt < 4; nt++) {
                int row = wx * 32 + nt * 8 + brow_l;
                int ch  = (kc + bk_h) ^ (row & 7);
                ldsm_x2(bfr[nt], sb + (uint32_t)(row * 128 + (ch << 4)));
            }
#pragma unroll
            for (int mt = 0; mt < 4; mt++)
#pragma unroll
                for (int nt = 0; nt < 4; nt++)
                    mma_tf32(acc[mt][nt], afr[mt], bfr[nt]);
        }
        int tn = t + 2;
        if (tn < ntiles) {
            int ws = rs + 2; if (ws >= 3) ws -= 3;
            NT_LOAD(ws, tn * 32);
        }
        cp_commit();
        rs++; if (rs == 3) rs = 0;
    }
#undef NT_LOAD

    int row0 = blockIdx.y * 128 + wy * 64;
    int col0 = blockIdx.x * 128 + wx * 32;
#pragma unroll
    for (int mt = 0; mt < 4; mt++) {
        int r1 = row0 + mt * 16 + grp;
        int r2 = r1 + 8;
#pragma unroll
        for (int nt = 0; nt < 4; nt++) {
            int cc = col0 + nt * 8 + l4 * 2;
            float e0 = acc[mt][nt][0], o0 = acc[mt][nt][1];
            float e1 = acc[mt][nt][2], o1 = acc[mt][nt][3];
            if (rope) {
                int p  = cc >> 1;
                int t1 = r1 & (TT - 1), t2 = r2 & (TT - 1);
                float c1v = cosT[t1 * HALF_D + p], s1v = sinT[t1 * HALF_D + p];
                float c2v = cosT[t2 * HALF_D + p], s2v = sinT[t2 * HALF_D + p];
                float ne0 = e0 * c1v - o0 * s1v, no0 = e0 * s1v + o0 * c1v;
                float ne1 = e1 * c2v - o1 * s2v, no1 = e1 * s2v + o1 * c2v;
                e0 = ne0; o0 = no0; e1 = ne1; o1 = no1;
            }
            if (qkv) {  // pre-round for downstream GEMM operand use
                e0 = tf32f(e0); o0 = tf32f(o0);
                e1 = tf32f(e1); o1 = tf32f(o1);
            }
            *(float2*)(Cp + (long long)r1 * ldc + cc) = make_float2(e0, o0);
            *(float2*)(Cp + (long long)r2 * ldc + cc) = make_float2(e1, o1);
        }
    }
}

// ---------------------------------------------------------------------------
// TF32 MMA GEMM, NN: C[M,N] = A[M,K]*B[K,N]. Inputs already tf32-rounded.
// K bounded to min((by+2)*128, K) — matches softmax zero-fill. 3-stage pipe.
// A swizzled as NT; B linear [k][136] (conflict-free scalar frag loads).
// ---------------------------------------------------------------------------
__global__ __launch_bounds__(256, 2) void mma_nn(
    const float* __restrict__ A, const float* __restrict__ B, float* __restrict__ C,
    int K, int lda, int ldb, int ldc,
    long long sA, long long sB, long long sC)
{
    const float* Ab = A + (long long)blockIdx.z * sA + (long long)blockIdx.y * 128 * lda;
    const float* Bb = B + (long long)blockIdx.z * sB + (long long)blockIdx.x * 128;
    float*       Cb = C + (long long)blockIdx.z * sC;

    int Kend = min(((int)blockIdx.y + 2) * 128, K);
    int ntiles = Kend >> 5;

    extern __shared__ float sm[];
    uint32_t su = (uint32_t)__cvta_generic_to_shared(sm);

    int tid = threadIdx.x, lane = tid & 31, warp = tid >> 5;
    int wy = warp >> 2, wx = warp & 3;
    int grp = lane >> 2, l4 = lane & 3;

    int arow_l = lane & 15;
    int ak_h   = lane >> 4;

    float acc[4][4][4];
#pragma unroll
    for (int mt = 0; mt < 4; mt++)
#pragma unroll
        for (int nt = 0; nt < 4; nt++)
#pragma unroll
            for (int j = 0; j < 4; j++) acc[mt][nt][j] = 0.f;

    // stage stride 33792B: A 16384B, B 17408B (32 x 136 floats)
#define NN_LOAD(stage, k0)                                                      \
    {                                                                           \
        uint32_t sa_ = su + (stage) * 33792;                                    \
        _Pragma("unroll")                                                       \
        for (int l = 0; l < 4; l++) {                                           \
            int v = tid + l * 256;                                             \
            int r = v >> 3, c4 = v & 7;                                        \
            uint32_t off = (uint32_t)(r * 128 + ((c4 ^ (r & 7)) << 4));        \
            cp16(sa_ + off, Ab + (long long)r * lda + (k0) + c4 * 4);          \
            int br = v >> 5, bc = (v & 31) * 4;                                \
            cp16(sa_ + 16384 + (uint32_t)((br * 136 + bc) * 4),                \
                 Bb + (long long)((k0) + br) * ldb + bc);                       \
        }                                                                       \
    }

    NN_LOAD(0, 0);  cp_commit();
    NN_LOAD(1, 32); cp_commit();

    int rs = 0;
    for (int t = 0; t < ntiles; t++) {
        cp_wait1();
        __syncthreads();
        uint32_t sa = su + rs * 33792;
        const float* bsf = sm + rs * 8448 + 4096;
#pragma unroll
        for (int ks = 0; ks < 4; ks++) {
            int kc = ks * 2;
            int kb = ks * 8;
            uint32_t afr[4][4], bfr[4][2];
#pragma unroll
            for (int mt = 0; mt < 4; mt++) {
                int row = wy * 64 + mt * 16 + arow_l;
                int ch  = (kc + ak_h) ^ (row & 7);
                ldsm_x4(afr[mt], sa + (uint32_t)(row * 128 + (ch << 4)));
            }
#pragma unroll
            for (int nt = 0; nt < 4; nt++) {
                int n = wx * 32 + nt * 8 + grp;
                bfr[nt][0] = __float_as_uint(bsf[(kb + l4) * 136 + n]);
                bfr[nt][1] = __float_as_uint(bsf[(kb + l4 + 4) * 136 + n]);
            }
#pragma unroll
            for (int mt = 0; mt < 4; mt++)
#pragma unroll
                for (int nt = 0; nt < 4; nt++)
                    mma_tf32(acc[mt][nt], afr[mt], bfr[nt]);
        }
        int tn = t + 2;
        if (tn < ntiles) {
            int ws = rs + 2; if (ws >= 3) ws -= 3;
            NN_LOAD(ws, tn * 32);
        }
        cp_commit();
        rs++; if (rs == 3) rs = 0;
    }
#undef NN_LOAD

    int row0 = blockIdx.y * 128 + wy * 64;
    int col0 = blockIdx.x * 128 + wx * 32;
#pragma unroll
    for (int mt = 0; mt < 4; mt++) {
        int r1 = row0 + mt * 16 + grp;
        int r2 = r1 + 8;
#pragma unroll
        for (int nt = 0; nt < 4; nt++) {
            int cc = col0 + nt * 8 + l4 * 2;
            *(float2*)(Cb + (long long)r1 * ldc + cc) =
                make_float2(acc[mt][nt][0], acc[mt][nt][1]);
            *(float2*)(Cb + (long long)r2 * ldc + cc) =
                make_float2(acc[mt][nt][2], acc[mt][nt][3]);
        }
    }
}

// ---------------------------------------------------------------------------
// Row softmax over valid prefix j <= q+1 (tril k=1), scale 1/32.
// Emits tf32-rounded probs (PV GEMM operand); zero-fills to PV read bound.
// ---------------------------------------------------------------------------
__global__ __launch_bounds__(256) void softmax_rows(float* __restrict__ S)
{
    int row = blockIdx.x;                 // b*T + q
    int q   = row & (TT - 1);
    float* s = S + (size_t)row * TT;
    int n    = min(q + 2, TT);
    int zend = min((((q >> 7) + 2) << 7), TT);

    int tid = threadIdx.x;
    float vals[8];
    int cnt = 0;
    float m = -1e30f;
    for (int j = tid; j < n; j += 256) {
        float v = s[j];
        vals[cnt++] = v;
        m = fmaxf(m, v);
    }

    __shared__ float red[8];
#pragma unroll
    for (int o = 16; o; o >>= 1) m = fmaxf(m, __shfl_xor_sync(0xffffffffu, m, o));
    if ((tid & 31) == 0) red[tid >> 5] = m;
    __syncthreads();
    m = red[0];
#pragma unroll
    for (int w = 1; w < 8; w++) m = fmaxf(m, red[w]);
    __syncthreads();

    float sum = 0.f;
    for (int c = 0; c < cnt; c++) {
        float e = expf((vals[c] - m) * 0.03125f);
        vals[c] = e;
        sum += e;
    }
#pragma unroll
    for (int o = 16; o; o >>= 1) sum += __shfl_xor_sync(0xffffffffu, sum, o);
    if ((tid & 31) == 0) red[tid >> 5] = sum;
    __syncthreads();
    float tot = 0.f;
#pragma unroll
    for (int w = 0; w < 8; w++) tot += red[w];
    float inv = 1.0f / tot;

    cnt = 0;
    for (int j = tid; j < n; j += 256) s[j] = tf32f(vals[cnt++] * inv);
    for (int j = n + tid; j < zend; j += 256) s[j] = 0.f;
}

// ---------------------------------------------------------------------------
// Launch: table + pre-round -> fused QKV (rope) -> scores -> softmax -> PV
// ---------------------------------------------------------------------------
extern "C" void kernel_launch(void* const* d_in, const int* in_sizes, int n_in,
                              void* d_out, int out_size)
{
    const float* x  = (const float*)d_in[0];
    const float* Wq = (const float*)d_in[1];
    const float* Wk = (const float*)d_in[2];
    const float* Wv = (const float*)d_in[3];
    float* out = (float*)d_out;

    float *Q, *K, *V, *S, *cT, *sT;
    cudaGetSymbolAddress((void**)&Q,  g_Q);
    cudaGetSymbolAddress((void**)&K,  g_K);
    cudaGetSymbolAddress((void**)&V,  g_V);
    cudaGetSymbolAddress((void**)&S,  g_S);
    cudaGetSymbolAddress((void**)&cT, g_cosT);
    cudaGetSymbolAddress((void**)&sT, g_sinT);

    // Alias tf32-rounded inputs into g_S (free until the scores GEMM runs)
    float* xt  = S;                              // 8M floats
    float* wqt = S + (size_t)8 * 1024 * 1024;    // 1M each
    float* wkt = wqt + 1024 * 1024;
    float* wvt = wkt + 1024 * 1024;

    cudaFuncSetAttribute(mma_nt, cudaFuncAttributeMaxDynamicSharedMemorySize, 98304);
    cudaFuncSetAttribute(mma_nn, cudaFuncAttributeMaxDynamicSharedMemorySize, 101376);

    dim3 blk(256);
    const long long TD  = (long long)TT * DD;
    const long long TT2 = (long long)TT * TT;

    rope_table<<<(TT * HALF_D) / 256, blk>>>(cT, sT);

    const int NX4 = (BATCH * TT * DD) / 4;   // 2M float4
    const int NW4 = (DD * DD) / 4;           // 256K float4
    round_in<<<(NX4 + 255) / 256, blk>>>((const float4*)x,  (float4*)xt,  NX4);
    round_in<<<(NW4 + 255) / 256, blk>>>((const float4*)Wq, (float4*)wqt, NW4);
    round_in<<<(NW4 + 255) / 256, blk>>>((const float4*)Wk, (float4*)wkt, NW4);
    round_in<<<(NW4 + 255) / 256, blk>>>((const float4*)Wv, (float4*)wvt, NW4);

    // Fused QKV: z=0/1/2 -> Q/K/V; rope fused for Q,K; outputs tf32-rounded
    mma_nt<<<dim3(DD / 128, (BATCH * TT) / 128, 3), blk, 98304>>>(
        xt, wqt, wkt, wvt, Q, K, V,
        DD, DD, DD, DD, 0, 0, 0, 1, cT, sT);

    // Scores: S[b] = Qr[b]*Kr[b]^T (raw fp32 out; causal block skip)
    mma_nt<<<dim3(TT / 128, TT / 128, BATCH), blk, 98304>>>(
        Q, K, nullptr, nullptr, S, nullptr, nullptr,
        DD, DD, DD, TT, TD, TD, TT2, 0, cT, sT);

    // Softmax (scale 1/32, causal mask, tf32-rounded probs, zero-fill)
    softmax_rows<<<BATCH * TT, blk>>>(S);

    // Out: O[b] = P[b]*V[b] (K bounded per q-block; raw fp32 out)
    mma_nn<<<dim3(DD / 128, TT / 128, BATCH), blk, 101376>>>(
        S, V, out, TT, TT, DD, DD, TT2, TD, TD);
}

// round 13
// speedup vs baseline: 5.8823x; 1.0851x over previous
#include <cuda_runtime.h>
#include <math.h>
#include <stdint.h>

#define BATCH 4
#define TT    2048
#define DD    1024
#define HALF_D 512

// Scratch (allocation-free rule: __device__ globals)
__device__ float g_Q[(size_t)BATCH * TT * DD];   // 32 MB
__device__ float g_K[(size_t)BATCH * TT * DD];   // 32 MB
__device__ float g_V[(size_t)BATCH * TT * DD];   // 32 MB
__device__ float g_S[(size_t)BATCH * TT * TT];   // 64 MB (head aliased as x_t/W_t pre-scores)
__device__ float g_cosT[(size_t)HALF_D * TT];    // 4 MB, layout [pair][t]
__device__ float g_sinT[(size_t)HALF_D * TT];    // 4 MB

// ---------------------------------------------------------------------------
// helpers
// ---------------------------------------------------------------------------
__device__ __forceinline__ float tf32f(float x) {
    uint32_t y;
    asm("cvt.rna.tf32.f32 %0, %1;" : "=r"(y) : "f"(x));
    return __uint_as_float(y);
}
__device__ __forceinline__ void cp16(uint32_t dst, const void* src) {
    asm volatile("cp.async.cg.shared.global [%0], [%1], 16;" :: "r"(dst), "l"(src));
}
__device__ __forceinline__ void cp_commit() { asm volatile("cp.async.commit_group;"); }
__device__ __forceinline__ void cp_wait1()  { asm volatile("cp.async.wait_group 1;"); }

__device__ __forceinline__ uint32_t smem_u32(const void* p) {
    return (uint32_t)__cvta_generic_to_shared(p);
}

__device__ __forceinline__ void ldsm_x4(uint32_t f[4], uint32_t addr) {
    asm volatile("ldmatrix.sync.aligned.m8n8.x4.shared.b16 {%0,%1,%2,%3}, [%4];"
                 : "=r"(f[0]), "=r"(f[1]), "=r"(f[2]), "=r"(f[3]) : "r"(addr));
}
__device__ __forceinline__ void ldsm_x2(uint32_t f[2], uint32_t addr) {
    asm volatile("ldmatrix.sync.aligned.m8n8.x2.shared.b16 {%0,%1}, [%2];"
                 : "=r"(f[0]), "=r"(f[1]) : "r"(addr));
}
__device__ __forceinline__ void mma_tf32(float c[4], const uint32_t a[4],
                                         const uint32_t b[2]) {
    asm volatile(
        "mma.sync.aligned.m16n8k8.row.col.f32.tf32.tf32.f32 "
        "{%0,%1,%2,%3},{%4,%5,%6,%7},{%8,%9},{%0,%1,%2,%3};"
        : "+f"(c[0]), "+f"(c[1]), "+f"(c[2]), "+f"(c[3])
        : "r"(a[0]), "r"(a[1]), "r"(a[2]), "r"(a[3]), "r"(b[0]), "r"(b[1]));
}

// FFMA-only exp (v <= 0): e^v = 2^(v*log2e); deg-5 poly, no MUFU.
__device__ __forceinline__ float fexp(float v) {
    float y = fmaxf(v * 1.4426950408889634f, -120.f);
    float r = rintf(y);
    float f = y - r;                      // |f| <= 0.5
    float fl = f * 0.6931471805599453f;   // f*ln2, |fl| <= 0.347
    float p = 1.3888888888888889e-3f;     // 1/720
    p = fmaf(p, fl, 8.3333333333333333e-3f);
    p = fmaf(p, fl, 4.1666666666666664e-2f);
    p = fmaf(p, fl, 1.6666666666666666e-1f);
    p = fmaf(p, fl, 5.0e-1f);
    p = fmaf(p, fl, 1.0f);
    p = fmaf(p, fl, 1.0f);                // e^(fl) Taylor deg 6, err ~3e-7
    return __int_as_float(((int)r + 127) << 23) * p;
}

// ---------------------------------------------------------------------------
// Fused setup: tf32 pre-round of x/Wq/Wk/Wv + RoPE cos/sin table [pair][t].
// Blocks [0,8192): x; [8192,11264): weights; [11264,15360): table.
// Table: theta computed ONCE per block in fp64 (512 exps total), angle
// rounded fp32 (matches reference), fp64 range-reduce, sinf/cosf.
// ---------------------------------------------------------------------------
__global__ __launch_bounds__(256) void setup_kernel(
    const float4* __restrict__ x,
    const float4* __restrict__ Wq, const float4* __restrict__ Wk,
    const float4* __restrict__ Wv,
    float4* __restrict__ xt,
    float4* __restrict__ wqt, float4* __restrict__ wkt, float4* __restrict__ wvt,
    float* __restrict__ cosT, float* __restrict__ sinT)
{
    int b = blockIdx.x, tid = threadIdx.x;
    if (b < 11264) {
        const float4* s; float4* d; int i;
        if (b < 8192) { s = x; d = xt; i = b * 256 + tid; }
        else {
            int w = (b - 8192) >> 10, o = (b - 8192) & 1023;
            s = (w == 0) ? Wq : ((w == 1) ? Wk : Wv);
            d = (w == 0) ? wqt : ((w == 1) ? wkt : wvt);
            i = o * 256 + tid;
        }
        float4 v = s[i];
        v.x = tf32f(v.x); v.y = tf32f(v.y);
        v.z = tf32f(v.z); v.w = tf32f(v.w);
        d[i] = v;
    } else {
        int idx = (b - 11264) * 256 + tid;       // < HALF_D*TT
        int pair = idx >> 11;                     // constant within block
        __shared__ double sh_theta;
        if (tid == 0)
            sh_theta = exp(-2.0 * (double)pair / (double)DD * 9.210340371976184);
        __syncthreads();
        float theta = (float)sh_theta;
        int t = idx & (TT - 1);
        float ang = (float)t * theta;             // fp32, matches reference
        double xx = (double)ang;
        double k = floor(xx * 0.15915494309189535);
        float r = (float)(xx - k * 6.283185307179586);
        cosT[idx] = cosf(r);
        sinT[idx] = sinf(r);
    }
}

// ---------------------------------------------------------------------------
// TF32 MMA GEMM, NT: C[M,N] = A[M,K]*B[N,K]^T. Inputs already tf32-rounded.
// 128x128 block, BK=32, 256 thr, 8 warps (2x4), warp tile 64x32.
// 3-stage cp.async pipeline, XOR-swizzled smem.
// qkv mode: z selects W / output; rope fused for z<2; outputs tf32-rounded.
// scores mode (qkv=0): z=batch, causal block skip, raw fp32 output.
// ---------------------------------------------------------------------------
__global__ __launch_bounds__(256, 2) void mma_nt(
    const float* __restrict__ A,
    const float* __restrict__ B0, const float* __restrict__ B1, const float* __restrict__ B2,
    float* __restrict__ C0, float* __restrict__ C1, float* __restrict__ C2,
    int K, int lda, int ldb, int ldc,
    long long sA, long long sB, long long sC,
    int qkv,
    const float* __restrict__ cosT, const float* __restrict__ sinT)
{
    int bz = blockIdx.z;
    const float* Ap = A;
    const float* Bp; float* Cp; int rope;
    if (qkv) {
        Bp = (bz == 0) ? B0 : ((bz == 1) ? B1 : B2);
        Cp = (bz == 0) ? C0 : ((bz == 1) ? C1 : C2);
        rope = (bz < 2) ? 1 : 0;
    } else {
        if ((int)blockIdx.x > (int)blockIdx.y + 1) return;
        Ap = A  + (long long)bz * sA;
        Bp = B0 + (long long)bz * sB;
        Cp = C0 + (long long)bz * sC;
        rope = 0;
    }
    const float* Ab = Ap + (long long)blockIdx.y * 128 * lda;
    const float* Bb = Bp + (long long)blockIdx.x * 128 * ldb;

    extern __shared__ float sm[];
    uint32_t su = smem_u32(sm);

    int tid = threadIdx.x, lane = tid & 31, warp = tid >> 5;
    int wy = warp >> 2, wx = warp & 3;
    int grp = lane >> 2, l4 = lane & 3;
    int arow_l = lane & 15, ak_h = lane >> 4;
    int brow_l = lane & 7,  bk_h = (lane >> 3) & 1;

    float acc[4][4][4];
#pragma unroll
    for (int mt = 0; mt < 4; mt++)
#pragma unroll
        for (int nt = 0; nt < 4; nt++)
#pragma unroll
            for (int j = 0; j < 4; j++) acc[mt][nt][j] = 0.f;

    int ntiles = K >> 5;

#define NT_LOAD(stage, k0)                                                    \
    {                                                                         \
        uint32_t sa_ = su + (stage) * 32768;                                  \
        _Pragma("unroll")                                                     \
        for (int l = 0; l < 4; l++) {                                         \
            int v = tid + l * 256;                                            \
            int r = v >> 3, c4 = v & 7;                                       \
            uint32_t off = (uint32_t)(r * 128 + ((c4 ^ (r & 7)) << 4));       \
            cp16(sa_ + off,         Ab + (long long)r * lda + (k0) + c4 * 4); \
            cp16(sa_ + 16384 + off, Bb + (long long)r * ldb + (k0) + c4 * 4); \
        }                                                                     \
    }

    NT_LOAD(0, 0);  cp_commit();
    NT_LOAD(1, 32); cp_commit();

    int rs = 0;
    for (int t = 0; t < ntiles; t++) {
        cp_wait1();
        __syncthreads();
        uint32_t sa = su + rs * 32768;
        uint32_t sb = sa + 16384;
#pragma unroll
        for (int ks = 0; ks < 4; ks++) {
            int kc = ks * 2;
            uint32_t afr[4][4], bfr[4][2];
#pragma unroll
            for (int mt = 0; mt < 4; mt++) {
                int row = wy * 64 + mt * 16 + arow_l;
                int ch  = (kc + ak_h) ^ (row & 7);
                ldsm_x4(afr[mt], sa + (uint32_t)(row * 128 + (ch << 4)));
            }
#pragma unroll
            for (int nt = 0; nt < 4; nt++) {
                int row = wx * 32 + nt * 8 + brow_l;
                int ch  = (kc + bk_h) ^ (row & 7);
                ldsm_x2(bfr[nt], sb + (uint32_t)(row * 128 + (ch << 4)));
            }
#pragma unroll
            for (int mt = 0; mt < 4; mt++)
#pragma unroll
                for (int nt = 0; nt < 4; nt++)
                    mma_tf32(acc[mt][nt], afr[mt], bfr[nt]);
        }
        int tn = t + 2;
        if (tn < ntiles) {
            int ws = rs + 2; if (ws >= 3) ws -= 3;
            NT_LOAD(ws, tn * 32);
        }
        cp_commit();
        rs++; if (rs == 3) rs = 0;
    }
#undef NT_LOAD

    int row0 = blockIdx.y * 128 + wy * 64;
    int col0 = blockIdx.x * 128 + wx * 32;
#pragma unroll
    for (int mt = 0; mt < 4; mt++) {
        int r1 = row0 + mt * 16 + grp;
        int r2 = r1 + 8;
#pragma unroll
        for (int nt = 0; nt < 4; nt++) {
            int cc = col0 + nt * 8 + l4 * 2;
            float e0 = acc[mt][nt][0], o0 = acc[mt][nt][1];
            float e1 = acc[mt][nt][2], o1 = acc[mt][nt][3];
            if (rope) {
                int p  = cc >> 1;
                int t1 = r1 & (TT - 1), t2 = r2 & (TT - 1);
                float c1v = cosT[(size_t)p * TT + t1], s1v = sinT[(size_t)p * TT + t1];
                float c2v = cosT[(size_t)p * TT + t2], s2v = sinT[(size_t)p * TT + t2];
                float ne0 = e0 * c1v - o0 * s1v, no0 = e0 * s1v + o0 * c1v;
                float ne1 = e1 * c2v - o1 * s2v, no1 = e1 * s2v + o1 * c2v;
                e0 = ne0; o0 = no0; e1 = ne1; o1 = no1;
            }
            if (qkv) {  // pre-round for downstream GEMM operand use
                e0 = tf32f(e0); o0 = tf32f(o0);
                e1 = tf32f(e1); o1 = tf32f(o1);
            }
            *(float2*)(Cp + (long long)r1 * ldc + cc) = make_float2(e0, o0);
            *(float2*)(Cp + (long long)r2 * ldc + cc) = make_float2(e1, o1);
        }
    }
}

// ---------------------------------------------------------------------------
// TF32 MMA GEMM, NN: C[M,N] = A[M,K]*B[K,N]. Inputs already tf32-rounded.
// K bounded to min((by+2)*128, K) — matches softmax zero-fill. 3-stage pipe.
// ---------------------------------------------------------------------------
__global__ __launch_bounds__(256, 2) void mma_nn(
    const float* __restrict__ A, const float* __restrict__ B, float* __restrict__ C,
    int K, int lda, int ldb, int ldc,
    long long sA, long long sB, long long sC)
{
    const float* Ab = A + (long long)blockIdx.z * sA + (long long)blockIdx.y * 128 * lda;
    const float* Bb = B + (long long)blockIdx.z * sB + (long long)blockIdx.x * 128;
    float*       Cb = C + (long long)blockIdx.z * sC;

    int Kend = min(((int)blockIdx.y + 2) * 128, K);
    int ntiles = Kend >> 5;

    extern __shared__ float sm[];
    uint32_t su = smem_u32(sm);

    int tid = threadIdx.x, lane = tid & 31, warp = tid >> 5;
    int wy = warp >> 2, wx = warp & 3;
    int grp = lane >> 2, l4 = lane & 3;
    int arow_l = lane & 15, ak_h = lane >> 4;

    float acc[4][4][4];
#pragma unroll
    for (int mt = 0; mt < 4; mt++)
#pragma unroll
        for (int nt = 0; nt < 4; nt++)
#pragma unroll
            for (int j = 0; j < 4; j++) acc[mt][nt][j] = 0.f;

#define NN_LOAD(stage, k0)                                                      \
    {                                                                           \
        uint32_t sa_ = su + (stage) * 33792;                                    \
        _Pragma("unroll")                                                       \
        for (int l = 0; l < 4; l++) {                                           \
            int v = tid + l * 256;                                             \
            int r = v >> 3, c4 = v & 7;                                        \
            uint32_t off = (uint32_t)(r * 128 + ((c4 ^ (r & 7)) << 4));        \
            cp16(sa_ + off, Ab + (long long)r * lda + (k0) + c4 * 4);          \
            int br = v >> 5, bc = (v & 31) * 4;                                \
            cp16(sa_ + 16384 + (uint32_t)((br * 136 + bc) * 4),                \
                 Bb + (long long)((k0) + br) * ldb + bc);                       \
        }                                                                       \
    }

    NN_LOAD(0, 0);  cp_commit();
    NN_LOAD(1, 32); cp_commit();

    int rs = 0;
    for (int t = 0; t < ntiles; t++) {
        cp_wait1();
        __syncthreads();
        uint32_t sa = su + rs * 33792;
        const float* bsf = sm + rs * 8448 + 4096;
#pragma unroll
        for (int ks = 0; ks < 4; ks++) {
            int kc = ks * 2;
            int kb = ks * 8;
            uint32_t afr[4][4], bfr[4][2];
#pragma unroll
            for (int mt = 0; mt < 4; mt++) {
                int row = wy * 64 + mt * 16 + arow_l;
                int ch  = (kc + ak_h) ^ (row & 7);
                ldsm_x4(afr[mt], sa + (uint32_t)(row * 128 + (ch << 4)));
            }
#pragma unroll
            for (int nt = 0; nt < 4; nt++) {
                int n = wx * 32 + nt * 8 + grp;
                bfr[nt][0] = __float_as_uint(bsf[(kb + l4) * 136 + n]);
                bfr[nt][1] = __float_as_uint(bsf[(kb + l4 + 4) * 136 + n]);
            }
#pragma unroll
            for (int mt = 0; mt < 4; mt++)
#pragma unroll
                for (int nt = 0; nt < 4; nt++)
                    mma_tf32(acc[mt][nt], afr[mt], bfr[nt]);
        }
        int tn = t + 2;
        if (tn < ntiles) {
            int ws = rs + 2; if (ws >= 3) ws -= 3;
            NN_LOAD(ws, tn * 32);
        }
        cp_commit();
        rs++; if (rs == 3) rs = 0;
    }
#undef NN_LOAD

    int row0 = blockIdx.y * 128 + wy * 64;
    int col0 = blockIdx.x * 128 + wx * 32;
#pragma unroll
    for (int mt = 0; mt < 4; mt++) {
        int r1 = row0 + mt * 16 + grp;
        int r2 = r1 + 8;
#pragma unroll
        for (int nt = 0; nt < 4; nt++) {
            int cc = col0 + nt * 8 + l4 * 2;
            *(float2*)(Cb + (long long)r1 * ldc + cc) =
                make_float2(acc[mt][nt][0], acc[mt][nt][1]);
            *(float2*)(Cb + (long long)r2 * ldc + cc) =
                make_float2(acc[mt][nt][2], acc[mt][nt][3]);
        }
    }
}

// ---------------------------------------------------------------------------
// Row softmax, vectorized float4 + poly exp (no MUFU). Valid prefix n=q+2,
// scale 1/32. Masked lanes get -1e30 -> exp ~ 2^-120 ~ 0 (PV contribution
// < 1e-37, far below tolerance). Zero-fills [nv4*4, zend) for PV reads.
// Emits tf32-rounded probs.
// ---------------------------------------------------------------------------
__global__ __launch_bounds__(256) void softmax_rows(float* __restrict__ S)
{
    int row = blockIdx.x;                 // b*T + q
    int q   = row & (TT - 1);
    float* s = S + (size_t)row * TT;
    int n    = min(q + 2, TT);
    int zend = min((((q >> 7) + 2) << 7), TT);
    int nv4  = (n + 3) >> 2;

    int tid = threadIdx.x;
    float4* s4 = (float4*)s;

    float4 v[2];
    float m = -1e30f;
#pragma unroll
    for (int it = 0; it < 2; it++) {
        int j = tid + it * 256;
        if (j < nv4) {
            float4 t = s4[j];
            int base = j * 4;
            if (base + 0 >= n) t.x = -1e30f;
            if (base + 1 >= n) t.y = -1e30f;
            if (base + 2 >= n) t.z = -1e30f;
            if (base + 3 >= n) t.w = -1e30f;
            v[it] = t;
            m = fmaxf(m, fmaxf(fmaxf(t.x, t.y), fmaxf(t.z, t.w)));
        } else {
            v[it] = make_float4(-1e30f, -1e30f, -1e30f, -1e30f);
        }
    }

    __shared__ float red[8];
#pragma unroll
    for (int o = 16; o; o >>= 1) m = fmaxf(m, __shfl_xor_sync(0xffffffffu, m, o));
    if ((tid & 31) == 0) red[tid >> 5] = m;
    __syncthreads();
    m = red[0];
#pragma unroll
    for (int w = 1; w < 8; w++) m = fmaxf(m, red[w]);
    __syncthreads();

    float sum = 0.f;
#pragma unroll
    for (int it = 0; it < 2; it++) {
        float4 t = v[it];
        t.x = fexp((t.x - m) * 0.03125f);
        t.y = fexp((t.y - m) * 0.03125f);
        t.z = fexp((t.z - m) * 0.03125f);
        t.w = fexp((t.w - m) * 0.03125f);
        v[it] = t;
        if (tid + it * 256 < nv4) sum += (t.x + t.y) + (t.z + t.w);
    }
#pragma unroll
    for (int o = 16; o; o >>= 1) sum += __shfl_xor_sync(0xffffffffu, sum, o);
    if ((tid & 31) == 0) red[tid >> 5] = sum;
    __syncthreads();
    float tot = 0.f;
#pragma unroll
    for (int w = 0; w < 8; w++) tot += red[w];
    float inv = 1.0f / tot;

#pragma unroll
    for (int it = 0; it < 2; it++) {
        int j = tid + it * 256;
        if (j < nv4) {
            float4 t = v[it];
            t.x = tf32f(t.x * inv); t.y = tf32f(t.y * inv);
            t.z = tf32f(t.z * inv); t.w = tf32f(t.w * inv);
            s4[j] = t;
        }
    }
    for (int j = nv4 * 4 + tid; j < zend; j += 256) s[j] = 0.f;
}

// ---------------------------------------------------------------------------
// Launch: setup -> fused QKV (rope) -> scores -> softmax -> PV
// ---------------------------------------------------------------------------
extern "C" void kernel_launch(void* const* d_in, const int* in_sizes, int n_in,
                              void* d_out, int out_size)
{
    const float* x  = (const float*)d_in[0];
    const float* Wq = (const float*)d_in[1];
    const float* Wk = (const float*)d_in[2];
    const float* Wv = (const float*)d_in[3];
    float* out = (float*)d_out;

    float *Q, *K, *V, *S, *cT, *sT;
    cudaGetSymbolAddress((void**)&Q,  g_Q);
    cudaGetSymbolAddress((void**)&K,  g_K);
    cudaGetSymbolAddress((void**)&V,  g_V);
    cudaGetSymbolAddress((void**)&S,  g_S);
    cudaGetSymbolAddress((void**)&cT, g_cosT);
    cudaGetSymbolAddress((void**)&sT, g_sinT);

    // Alias tf32-rounded inputs into g_S (free until the scores GEMM runs)
    float* xt  = S;                              // 8M floats
    float* wqt = S + (size_t)8 * 1024 * 1024;    // 1M each
    float* wkt = wqt + 1024 * 1024;
    float* wvt = wkt + 1024 * 1024;

    cudaFuncSetAttribute(mma_nt, cudaFuncAttributeMaxDynamicSharedMemorySize, 98304);
    cudaFuncSetAttribute(mma_nn, cudaFuncAttributeMaxDynamicSharedMemorySize, 101376);

    dim3 blk(256);
    const long long TD  = (long long)TT * DD;
    const long long TT2 = (long long)TT * TT;

    // Fused setup: pre-round x/W* + rope table (15360 blocks)
    setup_kernel<<<15360, blk>>>(
        (const float4*)x, (const float4*)Wq, (const float4*)Wk, (const float4*)Wv,
        (float4*)xt, (float4*)wqt, (float4*)wkt, (float4*)wvt, cT, sT);

    // Fused QKV: z=0/1/2 -> Q/K/V; rope fused for Q,K; outputs tf32-rounded
    mma_nt<<<dim3(DD / 128, (BATCH * TT) / 128, 3), blk, 98304>>>(
        xt, wqt, wkt, wvt, Q, K, V,
        DD, DD, DD, DD, 0, 0, 0, 1, cT, sT);

    // Scores: S[b] = Qr[b]*Kr[b]^T (raw fp32 out; causal block skip)
    mma_nt<<<dim3(TT / 128, TT / 128, BATCH), blk, 98304>>>(
        Q, K, nullptr, nullptr, S, nullptr, nullptr,
        DD, DD, DD, TT, TD, TD, TT2, 0, cT, sT);

    // Softmax (scale 1/32, causal mask, tf32-rounded probs, zero-fill)
    softmax_rows<<<BATCH * TT, blk>>>(S);

    // Out: O[b] = P[b]*V[b] (K bounded per q-block; raw fp32 out)
    mma_nn<<<dim3(DD / 128, TT / 128, BATCH), blk, 101376>>>(
        S, V, out, TT, TT, DD, DD, TT2, TD, TD);
}

// round 14
// speedup vs baseline: 10.2524x; 1.7429x over previous
#include <cuda_runtime.h>
#include <cuda_fp16.h>
#include <math.h>
#include <stdint.h>

#define BATCH 4
#define TT    2048
#define DD    1024
#define HALF_D 512

// Scratch (allocation-free rule: __device__ globals).
// Casts: Q/K/V used as __half (first 16MB of each). g_S layout over time:
//   [0 .. 8M floats)  = Sh (16M halfs): scores -> probs
//   [8M .. 12M)       = xh (8M halfs, fp16-rounded x)   } dead once scores run
//   [12M .. 13.5M)    = wqh/wkh/wvh (1M halfs each)     }
__device__ float g_Q[(size_t)BATCH * TT * DD];   // 32 MB
__device__ float g_K[(size_t)BATCH * TT * DD];   // 32 MB
__device__ float g_V[(size_t)BATCH * TT * DD];   // 32 MB
__device__ float g_S[(size_t)BATCH * TT * TT];   // 64 MB
__device__ float g_cosT[(size_t)HALF_D * TT];    // 4 MB, layout [pair][t]
__device__ float g_sinT[(size_t)HALF_D * TT];    // 4 MB

// ---------------------------------------------------------------------------
// helpers
// ---------------------------------------------------------------------------
__device__ __forceinline__ void cp16(uint32_t dst, const void* src) {
    asm volatile("cp.async.cg.shared.global [%0], [%1], 16;" :: "r"(dst), "l"(src));
}
__device__ __forceinline__ void cp_commit() { asm volatile("cp.async.commit_group;"); }
__device__ __forceinline__ void cp_wait1()  { asm volatile("cp.async.wait_group 1;"); }

__device__ __forceinline__ uint32_t smem_u32(const void* p) {
    return (uint32_t)__cvta_generic_to_shared(p);
}
__device__ __forceinline__ void ldsm_x4(uint32_t f[4], uint32_t addr) {
    asm volatile("ldmatrix.sync.aligned.m8n8.x4.shared.b16 {%0,%1,%2,%3}, [%4];"
                 : "=r"(f[0]), "=r"(f[1]), "=r"(f[2]), "=r"(f[3]) : "r"(addr));
}
__device__ __forceinline__ void ldsm_x2(uint32_t f[2], uint32_t addr) {
    asm volatile("ldmatrix.sync.aligned.m8n8.x2.shared.b16 {%0,%1}, [%2];"
                 : "=r"(f[0]), "=r"(f[1]) : "r"(addr));
}
__device__ __forceinline__ void ldsm_x2_t(uint32_t f[2], uint32_t addr) {
    asm volatile("ldmatrix.sync.aligned.m8n8.x2.trans.shared.b16 {%0,%1}, [%2];"
                 : "=r"(f[0]), "=r"(f[1]) : "r"(addr));
}
// fp16 MMA, fp32 accumulate: m16n8k16
__device__ __forceinline__ void mma_f16(float c[4], const uint32_t a[4],
                                        const uint32_t b[2]) {
    asm volatile(
        "mma.sync.aligned.m16n8k16.row.col.f32.f16.f16.f32 "
        "{%0,%1,%2,%3},{%4,%5,%6,%7},{%8,%9},{%0,%1,%2,%3};"
        : "+f"(c[0]), "+f"(c[1]), "+f"(c[2]), "+f"(c[3])
        : "r"(a[0]), "r"(a[1]), "r"(a[2]), "r"(a[3]), "r"(b[0]), "r"(b[1]));
}

// FFMA-only exp (v <= 0): e^v = 2^(v*log2e); no MUFU.
__device__ __forceinline__ float fexp(float v) {
    float y = fmaxf(v * 1.4426950408889634f, -120.f);
    float r = rintf(y);
    float fl = (y - r) * 0.6931471805599453f;
    float p = 1.3888888888888889e-3f;
    p = fmaf(p, fl, 8.3333333333333333e-3f);
    p = fmaf(p, fl, 4.1666666666666664e-2f);
    p = fmaf(p, fl, 1.6666666666666666e-1f);
    p = fmaf(p, fl, 5.0e-1f);
    p = fmaf(p, fl, 1.0f);
    p = fmaf(p, fl, 1.0f);
    return __int_as_float(((int)r + 127) << 23) * p;
}

// ---------------------------------------------------------------------------
// Fused setup: fp16-round x/Wq/Wk/Wv + RoPE cos/sin table [pair][t].
// Blocks [0,4096): x (8 floats/thread); [4096,5632): weights; rest: table.
// ---------------------------------------------------------------------------
__global__ __launch_bounds__(256) void setup_kernel(
    const float4* __restrict__ x,
    const float4* __restrict__ Wq, const float4* __restrict__ Wk,
    const float4* __restrict__ Wv,
    __half2* __restrict__ xh,
    __half2* __restrict__ wqh, __half2* __restrict__ wkh, __half2* __restrict__ wvh,
    float* __restrict__ cosT, float* __restrict__ sinT)
{
    int b = blockIdx.x, tid = threadIdx.x;
    if (b < 5632) {
        const float4* s; __half2* d; int i8;
        if (b < 4096) { s = x; d = xh; i8 = b * 256 + tid; }
        else {
            int wi = b - 4096;
            int w = wi >> 9, o = wi & 511;
            s = (w == 0) ? Wq : ((w == 1) ? Wk : Wv);
            d = (w == 0) ? wqh : ((w == 1) ? wkh : wvh);
            i8 = o * 256 + tid;
        }
        float4 a = s[i8 * 2], c = s[i8 * 2 + 1];
        d[i8 * 4 + 0] = __floats2half2_rn(a.x, a.y);
        d[i8 * 4 + 1] = __floats2half2_rn(a.z, a.w);
        d[i8 * 4 + 2] = __floats2half2_rn(c.x, c.y);
        d[i8 * 4 + 3] = __floats2half2_rn(c.z, c.w);
    } else {
        int idx = (b - 5632) * 256 + tid;         // < HALF_D*TT
        int pair = idx >> 11;                      // constant within block
        __shared__ double sh_theta;
        if (tid == 0)
            sh_theta = exp(-2.0 * (double)pair / (double)DD * 9.210340371976184);
        __syncthreads();
        float theta = (float)sh_theta;
        int t = idx & (TT - 1);
        float ang = (float)t * theta;              // fp32, matches reference
        double xx = (double)ang;
        double k = floor(xx * 0.15915494309189535);
        float r = (float)(xx - k * 6.283185307179586);
        cosT[idx] = cosf(r);
        sinT[idx] = sinf(r);
    }
}

// ---------------------------------------------------------------------------
// FP16 MMA GEMM, NT: C[M,N] = A[M,K]*B[N,K]^T (both K-contiguous halfs).
// 128x128 tile, BK=64 halfs (128B rows), 3-stage cp.async, XOR swizzle.
// qkv mode: z selects W/out; rope fused for z<2; outputs __half.
// scores mode (qkv=0): z=batch, causal block skip, __half output.
// ---------------------------------------------------------------------------
__global__ __launch_bounds__(256, 2) void mma_nt(
    const __half* __restrict__ A,
    const __half* __restrict__ B0, const __half* __restrict__ B1,
    const __half* __restrict__ B2,
    __half* __restrict__ C0, __half* __restrict__ C1, __half* __restrict__ C2,
    int K, int lda, int ldb, int ldc,
    long long sA, long long sB, long long sC,
    int qkv,
    const float* __restrict__ cosT, const float* __restrict__ sinT)
{
    int bz = blockIdx.z;
    const __half* Ap = A;
    const __half* Bp; __half* Cp; int rope;
    if (qkv) {
        Bp = (bz == 0) ? B0 : ((bz == 1) ? B1 : B2);
        Cp = (bz == 0) ? C0 : ((bz == 1) ? C1 : C2);
        rope = (bz < 2) ? 1 : 0;
    } else {
        if ((int)blockIdx.x > (int)blockIdx.y + 1) return;
        Ap = A  + (long long)bz * sA;
        Bp = B0 + (long long)bz * sB;
        Cp = C0 + (long long)bz * sC;
        rope = 0;
    }
    const __half* Ab = Ap + (long long)blockIdx.y * 128 * lda;
    const __half* Bb = Bp + (long long)blockIdx.x * 128 * ldb;

    extern __shared__ char sm[];
    uint32_t su = smem_u32(sm);

    int tid = threadIdx.x, lane = tid & 31, warp = tid >> 5;
    int wy = warp >> 2, wx = warp & 3;
    int grp = lane >> 2, l4 = lane & 3;
    int arow_l = lane & 15, ak_h = lane >> 4;
    int brow_l = lane & 7,  bk_h = (lane >> 3) & 1;

    float acc[4][4][4];
#pragma unroll
    for (int mt = 0; mt < 4; mt++)
#pragma unroll
        for (int nt = 0; nt < 4; nt++)
#pragma unroll
            for (int j = 0; j < 4; j++) acc[mt][nt][j] = 0.f;

    int ntiles = K >> 6;   // BK=64 halfs

    // stage: A 128x128B (16KB) + B 128x128B (16KB) = 32KB
#define NT_LOAD(stage, k0)                                                    \
    {                                                                         \
        uint32_t sa_ = su + (stage) * 32768;                                  \
        _Pragma("unroll")                                                     \
        for (int l = 0; l < 4; l++) {                                         \
            int v = tid + l * 256;                                            \
            int r = v >> 3, c4 = v & 7;                                       \
            uint32_t off = (uint32_t)(r * 128 + ((c4 ^ (r & 7)) << 4));       \
            cp16(sa_ + off,         Ab + (long long)r * lda + (k0) + c4 * 8); \
            cp16(sa_ + 16384 + off, Bb + (long long)r * ldb + (k0) + c4 * 8); \
        }                                                                     \
    }

    NT_LOAD(0, 0);  cp_commit();
    NT_LOAD(1, 64); cp_commit();

    int rs = 0;
    for (int t = 0; t < ntiles; t++) {
        cp_wait1();
        __syncthreads();
        uint32_t sa = su + rs * 32768;
        uint32_t sb = sa + 16384;
#pragma unroll
        for (int ks = 0; ks < 4; ks++) {       // k16 per step
            int kc = ks * 2;                   // 16B chunk index
            uint32_t afr[4][4], bfr[4][2];
#pragma unroll
            for (int mt = 0; mt < 4; mt++) {
                int row = wy * 64 + mt * 16 + arow_l;
                int ch  = (kc + ak_h) ^ (row & 7);
                ldsm_x4(afr[mt], sa + (uint32_t)(row * 128 + (ch << 4)));
            }
#pragma unroll
            for (int nt = 0; nt < 4; nt++) {
                int row = wx * 32 + nt * 8 + brow_l;
                int ch  = (kc + bk_h) ^ (row & 7);
                ldsm_x2(bfr[nt], sb + (uint32_t)(row * 128 + (ch << 4)));
            }
#pragma unroll
            for (int mt = 0; mt < 4; mt++)
#pragma unroll
                for (int nt = 0; nt < 4; nt++)
                    mma_f16(acc[mt][nt], afr[mt], bfr[nt]);
        }
        int tn = t + 2;
        if (tn < ntiles) {
            int ws = rs + 2; if (ws >= 3) ws -= 3;
            NT_LOAD(ws, tn * 64);
        }
        cp_commit();
        rs++; if (rs == 3) rs = 0;
    }
#undef NT_LOAD

    int row0 = blockIdx.y * 128 + wy * 64;
    int col0 = blockIdx.x * 128 + wx * 32;
#pragma unroll
    for (int mt = 0; mt < 4; mt++) {
        int r1 = row0 + mt * 16 + grp;
        int r2 = r1 + 8;
#pragma unroll
        for (int nt = 0; nt < 4; nt++) {
            int cc = col0 + nt * 8 + l4 * 2;
            float e0 = acc[mt][nt][0], o0 = acc[mt][nt][1];
            float e1 = acc[mt][nt][2], o1 = acc[mt][nt][3];
            if (rope) {
                int p  = cc >> 1;
                int t1 = r1 & (TT - 1), t2 = r2 & (TT - 1);
                float c1v = cosT[(size_t)p * TT + t1], s1v = sinT[(size_t)p * TT + t1];
                float c2v = cosT[(size_t)p * TT + t2], s2v = sinT[(size_t)p * TT + t2];
                float ne0 = e0 * c1v - o0 * s1v, no0 = e0 * s1v + o0 * c1v;
                float ne1 = e1 * c2v - o1 * s2v, no1 = e1 * s2v + o1 * c2v;
                e0 = ne0; o0 = no0; e1 = ne1; o1 = no1;
            }
            *(__half2*)(Cp + (long long)r1 * ldc + cc) = __floats2half2_rn(e0, o0);
            *(__half2*)(Cp + (long long)r2 * ldc + cc) = __floats2half2_rn(e1, o1);
        }
    }
}

// ---------------------------------------------------------------------------
// FP16 MMA GEMM, NN: C[M,N] = A[M,K]*B[K,N], fp32 output.
// A (P) K-contiguous halfs; B (V) N-contiguous halfs — B frag via
// ldmatrix.trans on a [k][136]-half padded tile (272B rows, conflict-free).
// K bounded to min((by+2)*128, K) — matches softmax zero-fill.
// ---------------------------------------------------------------------------
__global__ __launch_bounds__(256, 2) void mma_nn(
    const __half* __restrict__ A, const __half* __restrict__ B,
    float* __restrict__ C,
    int K, int lda, int ldb, int ldc,
    long long sA, long long sB, long long sC)
{
    const __half* Ab = A + (long long)blockIdx.z * sA + (long long)blockIdx.y * 128 * lda;
    const __half* Bb = B + (long long)blockIdx.z * sB + (long long)blockIdx.x * 128;
    float*        Cb = C + (long long)blockIdx.z * sC;

    int Kend = min(((int)blockIdx.y + 2) * 128, K);
    int ntiles = Kend >> 6;

    extern __shared__ char sm[];
    uint32_t su = smem_u32(sm);

    int tid = threadIdx.x, lane = tid & 31, warp = tid >> 5;
    int wy = warp >> 2, wx = warp & 3;
    int grp = lane >> 2, l4 = lane & 3;
    int arow_l = lane & 15, ak_h = lane >> 4;
    int lan16 = lane & 15;

    float acc[4][4][4];
#pragma unroll
    for (int mt = 0; mt < 4; mt++)
#pragma unroll
        for (int nt = 0; nt < 4; nt++)
#pragma unroll
            for (int j = 0; j < 4; j++) acc[mt][nt][j] = 0.f;

    // stage: A 16384B + B 64*272B = 17408B -> 33792B
#define NN_LOAD(stage, k0)                                                      \
    {                                                                           \
        uint32_t sa_ = su + (stage) * 33792;                                    \
        _Pragma("unroll")                                                       \
        for (int l = 0; l < 4; l++) {                                           \
            int v = tid + l * 256;                                              \
            int r = v >> 3, c4 = v & 7;                                         \
            uint32_t off = (uint32_t)(r * 128 + ((c4 ^ (r & 7)) << 4));         \
            cp16(sa_ + off, Ab + (long long)r * lda + (k0) + c4 * 8);           \
            int br = v >> 4, bc = (v & 15) * 8;                                 \
            cp16(sa_ + 16384 + (uint32_t)(br * 272 + bc * 2),                   \
                 Bb + (long long)((k0) + br) * ldb + bc);                       \
        }                                                                       \
    }

    NN_LOAD(0, 0);  cp_commit();
    NN_LOAD(1, 64); cp_commit();

    int rs = 0;
    for (int t = 0; t < ntiles; t++) {
        cp_wait1();
        __syncthreads();
        uint32_t sa = su + rs * 33792;
        uint32_t sb = sa + 16384;
#pragma unroll
        for (int ks = 0; ks < 4; ks++) {
            int kc = ks * 2;
            int kb = ks * 16;                  // k offset in halfs
            uint32_t afr[4][4], bfr[4][2];
#pragma unroll
            for (int mt = 0; mt < 4; mt++) {
                int row = wy * 64 + mt * 16 + arow_l;
                int ch  = (kc + ak_h) ^ (row & 7);
                ldsm_x4(afr[mt], sa + (uint32_t)(row * 128 + (ch << 4)));
            }
#pragma unroll
            for (int nt = 0; nt < 4; nt++) {
                int n0 = wx * 32 + nt * 8;
                int krow = kb + lan16;
                ldsm_x2_t(bfr[nt], sb + (uint32_t)(krow * 272 + n0 * 2));
            }
#pragma unroll
            for (int mt = 0; mt < 4; mt++)
#pragma unroll
                for (int nt = 0; nt < 4; nt++)
                    mma_f16(acc[mt][nt], afr[mt], bfr[nt]);
        }
        int tn = t + 2;
        if (tn < ntiles) {
            int ws = rs + 2; if (ws >= 3) ws -= 3;
            NN_LOAD(ws, tn * 64);
        }
        cp_commit();
        rs++; if (rs == 3) rs = 0;
    }
#undef NN_LOAD

    int row0 = blockIdx.y * 128 + wy * 64;
    int col0 = blockIdx.x * 128 + wx * 32;
#pragma unroll
    for (int mt = 0; mt < 4; mt++) {
        int r1 = row0 + mt * 16 + grp;
        int r2 = r1 + 8;
#pragma unroll
        for (int nt = 0; nt < 4; nt++) {
            int cc = col0 + nt * 8 + l4 * 2;
            *(float2*)(Cb + (long long)r1 * ldc + cc) =
                make_float2(acc[mt][nt][0], acc[mt][nt][1]);
            *(float2*)(Cb + (long long)r2 * ldc + cc) =
                make_float2(acc[mt][nt][2], acc[mt][nt][3]);
        }
    }
}

// ---------------------------------------------------------------------------
// Row softmax on __half scores. One uint4 (8 halfs) per thread covers the
// whole 2048 row. Valid prefix n=q+2, scale 1/32, fp32 math, fp16 probs.
// Masked lanes -> -1e30 -> exp ~ 2^-120 ~ 0. Zero-fills to PV read bound.
// ---------------------------------------------------------------------------
__global__ __launch_bounds__(256) void softmax_rows(__half* __restrict__ S)
{
    int row = blockIdx.x;                 // b*T + q
    int q   = row & (TT - 1);
    __half* s = S + (size_t)row * TT;
    int n    = min(q + 2, TT);
    int zend = min((((q >> 7) + 2) << 7), TT);
    int nv8  = (n + 7) >> 3;

    int tid = threadIdx.x;
    uint4* s8 = (uint4*)s;

    float v[8];
    float m = -1e30f;
    if (tid < nv8) {
        uint4 u = s8[tid];
        __half2* h = (__half2*)&u;
        int base = tid * 8;
#pragma unroll
        for (int k = 0; k < 4; k++) {
            float2 f = __half22float2(h[k]);
            v[k*2]   = (base + k*2     < n) ? f.x : -1e30f;
            v[k*2+1] = (base + k*2 + 1 < n) ? f.y : -1e30f;
        }
#pragma unroll
        for (int k = 0; k < 8; k++) m = fmaxf(m, v[k]);
    } else {
#pragma unroll
        for (int k = 0; k < 8; k++) v[k] = -1e30f;
    }

    __shared__ float red[8];
#pragma unroll
    for (int o = 16; o; o >>= 1) m = fmaxf(m, __shfl_xor_sync(0xffffffffu, m, o));
    if ((tid & 31) == 0) red[tid >> 5] = m;
    __syncthreads();
    m = red[0];
#pragma unroll
    for (int w = 1; w < 8; w++) m = fmaxf(m, red[w]);
    __syncthreads();

    float sum = 0.f;
#pragma unroll
    for (int k = 0; k < 8; k++) {
        v[k] = fexp((v[k] - m) * 0.03125f);
        sum += v[k];
    }
    if (tid >= nv8) sum = 0.f;
#pragma unroll
    for (int o = 16; o; o >>= 1) sum += __shfl_xor_sync(0xffffffffu, sum, o);
    if ((tid & 31) == 0) red[tid >> 5] = sum;
    __syncthreads();
    float tot = 0.f;
#pragma unroll
    for (int w = 0; w < 8; w++) tot += red[w];
    float inv = 1.0f / tot;

    if (tid < nv8) {
        uint4 u;
        __half2* h = (__half2*)&u;
#pragma unroll
        for (int k = 0; k < 4; k++)
            h[k] = __floats2half2_rn(v[k*2] * inv, v[k*2+1] * inv);
        s8[tid] = u;
    }
    for (int j = nv8 * 8 + tid; j < zend; j += 256) s[j] = __ushort_as_half(0);
}

// ---------------------------------------------------------------------------
// Launch: setup -> fused QKV (rope) -> scores -> softmax -> PV
// ---------------------------------------------------------------------------
extern "C" void kernel_launch(void* const* d_in, const int* in_sizes, int n_in,
                              void* d_out, int out_size)
{
    const float* x  = (const float*)d_in[0];
    const float* Wq = (const float*)d_in[1];
    const float* Wk = (const float*)d_in[2];
    const float* Wv = (const float*)d_in[3];
    float* out = (float*)d_out;

    float *Qf, *Kf, *Vf, *S, *cT, *sT;
    cudaGetSymbolAddress((void**)&Qf, g_Q);
    cudaGetSymbolAddress((void**)&Kf, g_K);
    cudaGetSymbolAddress((void**)&Vf, g_V);
    cudaGetSymbolAddress((void**)&S,  g_S);
    cudaGetSymbolAddress((void**)&cT, g_cosT);
    cudaGetSymbolAddress((void**)&sT, g_sinT);

    __half* Qh = (__half*)Qf;
    __half* Kh = (__half*)Kf;
    __half* Vh = (__half*)Vf;
    __half* Sh = (__half*)S;                                  // 16M halfs
    __half* xh  = (__half*)(S + (size_t)8  * 1024 * 1024);    // 8M halfs
    __half* wqh = (__half*)(S + (size_t)12 * 1024 * 1024);    // 1M halfs each
    __half* wkh = wqh + 1024 * 1024;
    __half* wvh = wkh + 1024 * 1024;

    cudaFuncSetAttribute(mma_nt, cudaFuncAttributeMaxDynamicSharedMemorySize, 98304);
    cudaFuncSetAttribute(mma_nn, cudaFuncAttributeMaxDynamicSharedMemorySize, 101376);

    dim3 blk(256);
    const long long TD  = (long long)TT * DD;   // in halfs
    const long long TT2 = (long long)TT * TT;

    // Setup: fp16-round x/W* (5632 blocks) + rope table (4096 blocks)
    setup_kernel<<<5632 + 4096, blk>>>(
        (const float4*)x, (const float4*)Wq, (const float4*)Wk, (const float4*)Wv,
        (__half2*)xh, (__half2*)wqh, (__half2*)wkh, (__half2*)wvh, cT, sT);

    // Fused QKV: z=0/1/2 -> Q/K/V (half); rope fused for Q,K
    mma_nt<<<dim3(DD / 128, (BATCH * TT) / 128, 3), blk, 98304>>>(
        xh, wqh, wkh, wvh, Qh, Kh, Vh,
        DD, DD, DD, DD, 0, 0, 0, 1, cT, sT);

    // Scores: Sh[b] = Qr[b]*Kr[b]^T (half out; causal block skip)
    mma_nt<<<dim3(TT / 128, TT / 128, BATCH), blk, 98304>>>(
        Qh, Kh, nullptr, nullptr, Sh, nullptr, nullptr,
        DD, DD, DD, TT, TD, TD, TT2, 0, cT, sT);

    // Softmax (scale 1/32, causal mask, fp16 probs, zero-fill)
    softmax_rows<<<BATCH * TT, blk>>>(Sh);

    // Out: O[b] = P[b]*V[b] (K bounded per q-block; fp32 out)
    mma_nn<<<dim3(DD / 128, TT / 128, BATCH), blk, 101376>>>(
        Sh, Vh, out, TT, TT, DD, DD, TT2, TD, TD);
}